// round 16
// baseline (speedup 1.0000x reference)
#include <cuda_runtime.h>
#include <cuda_fp16.h>
#include <cstdint>

#define N_NODES 50000
#define N_EDGES 500000
#define HID 128

// ---------------- scratch (device globals) ------------------------------------
__device__ int      g_deg[N_NODES];
__device__ int      g_off[N_NODES + 1];
__device__ int      g_cursor[N_NODES];
__device__ int      g_bsum[256];
__device__ uint16_t g_srcs[N_EDGES];
__device__ __half   g_xh [(size_t)N_NODES * HID];
__device__ __half   g_agg[(size_t)N_NODES * HID];
__device__ __half   g_h1 [(size_t)N_NODES * HID];
__device__ __half   g_h2 [(size_t)N_NODES * HID];
__device__ __half   g_wh [81920];    // [W1l|W1r|W2l|W2r|Wcat3] fp16
__device__ float    g_b3cat[128];    // [0...0 | b3]

// ---------------- small helpers -----------------------------------------------
__device__ __forceinline__ uint32_t smem_u32(const void* p) {
    uint32_t a;
    asm("{ .reg .u64 t; cvta.to.shared.u64 t, %1; cvt.u32.u64 %0, t; }" : "=r"(a) : "l"(p));
    return a;
}

#define LDSM_X4(r, a) \
    asm volatile("ldmatrix.sync.aligned.m8n8.x4.shared.b16 {%0,%1,%2,%3}, [%4];" \
                 : "=r"((r)[0]), "=r"((r)[1]), "=r"((r)[2]), "=r"((r)[3]) : "r"(a))
#define LDSM_X4T(r0, r1, r2, r3, a) \
    asm volatile("ldmatrix.sync.aligned.m8n8.x4.trans.shared.b16 {%0,%1,%2,%3}, [%4];" \
                 : "=r"(r0), "=r"(r1), "=r"(r2), "=r"(r3) : "r"(a))

__device__ __forceinline__ void mma_f16(float* d, const uint32_t* a, const uint32_t* b) {
    asm volatile(
        "mma.sync.aligned.m16n8k16.row.col.f32.f16.f16.f32 "
        "{%0,%1,%2,%3}, {%4,%5,%6,%7}, {%8,%9}, {%0,%1,%2,%3};"
        : "+f"(d[0]), "+f"(d[1]), "+f"(d[2]), "+f"(d[3])
        : "r"(a[0]), "r"(a[1]), "r"(a[2]), "r"(a[3]), "r"(b[0]), "r"(b[1]));
}

__device__ __forceinline__ uint4 cvt8(const float* p) {
    float4 a = ((const float4*)p)[0], b = ((const float4*)p)[1];
    __half2 h0 = __float22half2_rn(make_float2(a.x, a.y));
    __half2 h1 = __float22half2_rn(make_float2(a.z, a.w));
    __half2 h2 = __float22half2_rn(make_float2(b.x, b.y));
    __half2 h3 = __float22half2_rn(make_float2(b.z, b.w));
    uint4 u;
    u.x = *(uint32_t*)&h0; u.y = *(uint32_t*)&h1;
    u.z = *(uint32_t*)&h2; u.w = *(uint32_t*)&h3;
    return u;
}

// ---------------- prep: conv_x + conv_w(+b3cat) + count_deg --------------------
__global__ void prep_kernel(const float* __restrict__ x, __half* __restrict__ xh, int xb,
                            const float* __restrict__ W1l, const float* __restrict__ W1r,
                            const float* __restrict__ W2l, const float* __restrict__ W2r,
                            const float* __restrict__ W3l, const float* __restrict__ W3r,
                            __half* __restrict__ wh,
                            const float* __restrict__ b3, float* __restrict__ b3cat,
                            const int* __restrict__ dst, int* __restrict__ deg, int E,
                            int total8) {
    int b = blockIdx.x, tid = threadIdx.x;
    if (b < xb) {
        int i = b * 256 + tid;
        if (i < total8)
            *(uint4*)(xh + (size_t)i * 8) = cvt8(x + (size_t)i * 8);
    } else if (b < xb + 40) {
        if (b == xb && tid < 128)
            b3cat[tid] = (tid < 64) ? 0.f : b3[tid - 64];
        int i = (b - xb) * 256 + tid;
        if (i < 10240) {
            int base = i * 8;
            const float* src;
            if      (base < 16384) { src = W1l + base;         }
            else if (base < 32768) { src = W1r + base - 16384; }
            else if (base < 49152) { src = W2l + base - 32768; }
            else if (base < 65536) { src = W2r + base - 49152; }
            else {
                int loc = base - 65536;         // Wcat: [128 k][128 c]
                int k = loc >> 7, c = loc & 127;
                src = (c < 64) ? (W3l + k * 64 + c) : (W3r + k * 64 + c - 64);
            }
            *(uint4*)(wh + base) = cvt8(src);
        }
    } else {
        // degree count, 4 edges per thread (fire-and-forget atomics)
        int e4 = (b - xb - 40) * 256 + tid;
        int base = e4 * 4;
        if (base + 3 < E) {
            int4 d = *(const int4*)(dst + base);
            atomicAdd(&deg[d.x], 1);
            atomicAdd(&deg[d.y], 1);
            atomicAdd(&deg[d.z], 1);
            atomicAdd(&deg[d.w], 1);
        } else if (base < E) {
            for (int k = base; k < E; k++) atomicAdd(&deg[dst[k]], 1);
        }
    }
}

// ---------------- two-kernel scan ----------------------------------------------
__device__ __forceinline__ int block_scan256(int v, int* ws) {
    int lane = threadIdx.x & 31, w = threadIdx.x >> 5;
    int x = v;
    #pragma unroll
    for (int o = 1; o < 32; o <<= 1) {
        int t = __shfl_up_sync(0xFFFFFFFFu, x, o);
        if (lane >= o) x += t;
    }
    if (lane == 31) ws[w] = x;
    __syncthreads();
    if (w == 0) {
        int y = (lane < 8) ? ws[lane] : 0;
        #pragma unroll
        for (int o = 1; o < 8; o <<= 1) {
            int t = __shfl_up_sync(0xFFFFFFFFu, y, o);
            if (lane >= o) y += t;
        }
        if (lane < 8) ws[lane] = y;
    }
    __syncthreads();
    int base = (w > 0) ? ws[w - 1] : 0;
    return x + base;
}

__global__ void scan_partial(const int* __restrict__ deg, int* __restrict__ off,
                             int* __restrict__ bsum, int N) {
    __shared__ int ws[8];
    int i = blockIdx.x * 256 + threadIdx.x;
    int v = (i < N) ? deg[i] : 0;
    int incl = block_scan256(v, ws);
    if (i < N) off[i] = incl - v;
    if (threadIdx.x == 255) bsum[blockIdx.x] = incl;
}

__device__ __forceinline__ int block_reduce256(int v, int* ws) {
    int lane = threadIdx.x & 31, w = threadIdx.x >> 5;
    #pragma unroll
    for (int o = 16; o > 0; o >>= 1) v += __shfl_down_sync(0xFFFFFFFFu, v, o);
    if (lane == 0) ws[w] = v;
    __syncthreads();
    if (w == 0) {
        int y = (lane < 8) ? ws[lane] : 0;
        #pragma unroll
        for (int o = 4; o > 0; o >>= 1) y += __shfl_down_sync(0xFFFFFFFFu, y, o);
        if (lane == 0) ws[0] = y;
    }
    __syncthreads();
    return ws[0];
}

__global__ void finish_off(int* __restrict__ off, int* __restrict__ cur,
                           const int* __restrict__ bsum, int N, int nblk) {
    __shared__ int ws[8];
    __shared__ int s_prefix;
    int b = blockIdx.x, t = threadIdx.x;
    int v = (t < b) ? bsum[t] : 0;
    int pre = block_reduce256(v, ws);
    if (t == 0) s_prefix = pre;
    __syncthreads();
    int i = b * 256 + t;
    if (i < N) {
        int val = off[i] + s_prefix;
        off[i] = val;
        cur[i] = val;
    }
    if (b == 0) {
        __syncthreads();
        int v2 = (t < nblk) ? bsum[t] : 0;
        int total = block_reduce256(v2, ws);
        if (t == 0) off[N] = total;
    }
}

// ---------------- CSR fill: 1 edge per thread (confirmed optimal) --------------
__global__ void fill_csr_kernel(const int* __restrict__ src, const int* __restrict__ dst,
                                int* __restrict__ cur, uint16_t* __restrict__ srcs, int E) {
    int e = blockIdx.x * blockDim.x + threadIdx.x;
    if (e < E) {
        int pos = atomicAdd(&cur[dst[e]], 1);
        srcs[pos] = (uint16_t)src[e];
    }
}

// ---------------- mean aggregation (warp/node, uint2, pairwise-8 tree) ---------
__global__ void agg_f16_kernel(const __half* __restrict__ x, __half* __restrict__ agg,
                               const int* __restrict__ off,
                               const uint16_t* __restrict__ srcs, int N) {
    int warp = (blockIdx.x * blockDim.x + threadIdx.x) >> 5;
    int lane = threadIdx.x & 31;
    if (warp >= N) return;
    int s = off[warp], e = off[warp + 1];
    float4 acc = make_float4(0.f, 0.f, 0.f, 0.f);
    int j = s;
    for (; j + 7 < e; j += 8) {
        uint2 p0 = *(const uint2*)(x + (size_t)srcs[j + 0] * HID + 4 * lane);
        uint2 p1 = *(const uint2*)(x + (size_t)srcs[j + 1] * HID + 4 * lane);
        uint2 p2 = *(const uint2*)(x + (size_t)srcs[j + 2] * HID + 4 * lane);
        uint2 p3 = *(const uint2*)(x + (size_t)srcs[j + 3] * HID + 4 * lane);
        uint2 p4 = *(const uint2*)(x + (size_t)srcs[j + 4] * HID + 4 * lane);
        uint2 p5 = *(const uint2*)(x + (size_t)srcs[j + 5] * HID + 4 * lane);
        uint2 p6 = *(const uint2*)(x + (size_t)srcs[j + 6] * HID + 4 * lane);
        uint2 p7 = *(const uint2*)(x + (size_t)srcs[j + 7] * HID + 4 * lane);
        __half2 slo = __hadd2(
            __hadd2(__hadd2(*(__half2*)&p0.x, *(__half2*)&p1.x),
                    __hadd2(*(__half2*)&p2.x, *(__half2*)&p3.x)),
            __hadd2(__hadd2(*(__half2*)&p4.x, *(__half2*)&p5.x),
                    __hadd2(*(__half2*)&p6.x, *(__half2*)&p7.x)));
        __half2 shi = __hadd2(
            __hadd2(__hadd2(*(__half2*)&p0.y, *(__half2*)&p1.y),
                    __hadd2(*(__half2*)&p2.y, *(__half2*)&p3.y)),
            __hadd2(__hadd2(*(__half2*)&p4.y, *(__half2*)&p5.y),
                    __hadd2(*(__half2*)&p6.y, *(__half2*)&p7.y)));
        float2 flo = __half22float2(slo);
        float2 fhi = __half22float2(shi);
        acc.x += flo.x; acc.y += flo.y; acc.z += fhi.x; acc.w += fhi.y;
    }
    if (j + 3 < e) {
        uint2 p0 = *(const uint2*)(x + (size_t)srcs[j + 0] * HID + 4 * lane);
        uint2 p1 = *(const uint2*)(x + (size_t)srcs[j + 1] * HID + 4 * lane);
        uint2 p2 = *(const uint2*)(x + (size_t)srcs[j + 2] * HID + 4 * lane);
        uint2 p3 = *(const uint2*)(x + (size_t)srcs[j + 3] * HID + 4 * lane);
        __half2 slo = __hadd2(__hadd2(*(__half2*)&p0.x, *(__half2*)&p1.x),
                              __hadd2(*(__half2*)&p2.x, *(__half2*)&p3.x));
        __half2 shi = __hadd2(__hadd2(*(__half2*)&p0.y, *(__half2*)&p1.y),
                              __hadd2(*(__half2*)&p2.y, *(__half2*)&p3.y));
        float2 flo = __half22float2(slo);
        float2 fhi = __half22float2(shi);
        acc.x += flo.x; acc.y += flo.y; acc.z += fhi.x; acc.w += fhi.y;
        j += 4;
    }
    for (; j < e; j++) {
        uint2 p0 = *(const uint2*)(x + (size_t)srcs[j] * HID + 4 * lane);
        float2 a0 = __half22float2(*(__half2*)&p0.x), a1 = __half22float2(*(__half2*)&p0.y);
        acc.x += a0.x; acc.y += a0.y; acc.z += a1.x; acc.w += a1.y;
    }
    float inv = 1.0f / (float)max(e - s, 1);
    __half2 o0 = __float22half2_rn(make_float2(acc.x * inv, acc.y * inv));
    __half2 o1 = __float22half2_rn(make_float2(acc.z * inv, acc.w * inv));
    uint2 o;
    o.x = *(uint32_t*)&o0; o.y = *(uint32_t*)&o1;
    *(uint2*)(agg + (size_t)warp * HID + 4 * lane) = o;
}

// ---------------- layer-3 final: out = mean-gather(p) + q ----------------------
__global__ void final_agg_kernel(const __half* __restrict__ ph, float* __restrict__ out,
                                 const int* __restrict__ off,
                                 const uint16_t* __restrict__ srcs, int N) {
    int warp = (blockIdx.x * blockDim.x + threadIdx.x) >> 5;
    int lane = threadIdx.x & 31;
    if (warp >= N) return;
    int s = off[warp], e = off[warp + 1];
    float2 acc = make_float2(0.f, 0.f);
    int j = s;
    for (; j + 7 < e; j += 8) {
        __half2 h0 = *(const __half2*)(ph + (size_t)srcs[j + 0] * HID + 2 * lane);
        __half2 h1 = *(const __half2*)(ph + (size_t)srcs[j + 1] * HID + 2 * lane);
        __half2 h2 = *(const __half2*)(ph + (size_t)srcs[j + 2] * HID + 2 * lane);
        __half2 h3 = *(const __half2*)(ph + (size_t)srcs[j + 3] * HID + 2 * lane);
        __half2 h4 = *(const __half2*)(ph + (size_t)srcs[j + 4] * HID + 2 * lane);
        __half2 h5 = *(const __half2*)(ph + (size_t)srcs[j + 5] * HID + 2 * lane);
        __half2 h6 = *(const __half2*)(ph + (size_t)srcs[j + 6] * HID + 2 * lane);
        __half2 h7 = *(const __half2*)(ph + (size_t)srcs[j + 7] * HID + 2 * lane);
        __half2 sh = __hadd2(__hadd2(__hadd2(h0, h1), __hadd2(h2, h3)),
                             __hadd2(__hadd2(h4, h5), __hadd2(h6, h7)));
        float2 f = __half22float2(sh);
        acc.x += f.x; acc.y += f.y;
    }
    if (j + 3 < e) {
        __half2 h0 = *(const __half2*)(ph + (size_t)srcs[j + 0] * HID + 2 * lane);
        __half2 h1 = *(const __half2*)(ph + (size_t)srcs[j + 1] * HID + 2 * lane);
        __half2 h2 = *(const __half2*)(ph + (size_t)srcs[j + 2] * HID + 2 * lane);
        __half2 h3 = *(const __half2*)(ph + (size_t)srcs[j + 3] * HID + 2 * lane);
        __half2 sh = __hadd2(__hadd2(h0, h1), __hadd2(h2, h3));
        float2 f = __half22float2(sh);
        acc.x += f.x; acc.y += f.y;
        j += 4;
    }
    for (; j < e; j++) {
        float2 f0 = __half22float2(*(const __half2*)(ph + (size_t)srcs[j] * HID + 2 * lane));
        acc.x += f0.x; acc.y += f0.y;
    }
    float inv = 1.0f / (float)max(e - s, 1);
    float2 q = __half22float2(*(const __half2*)(ph + (size_t)warp * HID + 64 + 2 * lane));
    *(float2*)(out + (size_t)warp * 64 + 2 * lane) =
        make_float2(acc.x * inv + q.x, acc.y * inv + q.y);
}

// ---------------- fp16 tensor-core GEMM with register-staged prefetch ----------
template <int OUTC, bool RELU, typename OT, int NCHUNK>
__global__ __launch_bounds__(256, 2)
void gemm_f16(const __half* __restrict__ agg, const __half* __restrict__ xin,
              const __half* __restrict__ Whl, const __half* __restrict__ Whr,
              const float* __restrict__ bias, OT* __restrict__ out, int N) {
    constexpr int NT = OUTC / 16;
    constexpr int BIT = (64 * (OUTC / 8)) / 256;   // B load iters: 4 or 2
    extern __shared__ char smem[];
    uint32_t sA = smem_u32(smem);
    uint32_t sB = sA + 16384;

    int tid = threadIdx.x, lane = tid & 31, wid = tid >> 5;
    int nb = blockIdx.x * 128;
    int wn = 32 * (wid >> 1);
    int wc = (OUTC / 2) * (wid & 1);
    int g  = lane >> 2;
    int t  = lane & 3;
    int lrow = lane & 7;
    int selA_r = ((lane >> 3) & 1) * 8;
    int selA_k = ((lane >> 4) & 1) * 8;
    int selB_k = ((lane >> 3) & 1) * 8;
    int selB_n = ((lane >> 4) & 1) * 8;

    uint4 ra[4];
    uint4 rb[BIT];

    auto ldAB = [&](int chunk) {
        const __half* Asrc = (chunk < 2) ? agg : xin;
        const __half* Wsrc = (chunk < 2) ? Whl : Whr;
        int kb = (chunk & 1) * 64;
        #pragma unroll
        for (int it = 0; it < 4; it++) {
            int idx = it * 256 + tid;
            int node = idx >> 3, u8 = idx & 7;
            int gn = min(nb + node, N - 1);
            ra[it] = *(const uint4*)(Asrc + (size_t)gn * HID + kb + 8 * u8);
        }
        #pragma unroll
        for (int it = 0; it < BIT; it++) {
            int idx = it * 256 + tid;
            int k = idx / (OUTC / 8), u = idx % (OUTC / 8);
            rb[it] = *(const uint4*)(Wsrc + (size_t)(kb + k) * OUTC + 8 * u);
        }
    };
    auto stAB = [&]() {
        #pragma unroll
        for (int it = 0; it < 4; it++) {
            int idx = it * 256 + tid;
            int node = idx >> 3, u8 = idx & 7;
            uint32_t o = node * 128 + ((u8 * 16) ^ ((node & 7) * 16));
            *(uint4*)(smem + o) = ra[it];
        }
        #pragma unroll
        for (int it = 0; it < BIT; it++) {
            int idx = it * 256 + tid;
            int k = idx / (OUTC / 8), u = idx % (OUTC / 8);
            uint32_t o = k * (2 * OUTC) + ((u * 16) ^ ((k & 7) * 16));
            *(uint4*)(smem + 16384 + o) = rb[it];
        }
    };

    float acc[2][NT][4];
    #pragma unroll
    for (int mt = 0; mt < 2; mt++)
        #pragma unroll
        for (int nt = 0; nt < NT; nt++)
            #pragma unroll
            for (int q = 0; q < 4; q++) acc[mt][nt][q] = 0.f;

    // prologue: chunk 0 into smem
    ldAB(0);
    stAB();
    __syncthreads();

    #pragma unroll
    for (int chunk = 0; chunk < NCHUNK; chunk++) {
        // prefetch next chunk's gmem data into registers (overlaps compute)
        if (chunk + 1 < NCHUNK) ldAB(chunk + 1);

        // compute current chunk from smem
        #pragma unroll
        for (int ks = 0; ks < 4; ks++) {
            int k0 = 16 * ks;
            uint32_t a[2][4];
            #pragma unroll
            for (int mt = 0; mt < 2; mt++) {
                int row = wn + 16 * mt + selA_r + lrow;
                int kc  = k0 + selA_k;
                uint32_t addr = sA + row * 128 + ((2 * kc) ^ ((row & 7) * 16));
                LDSM_X4(a[mt], addr);
            }
            uint32_t b[NT][2];
            #pragma unroll
            for (int p = 0; p < NT / 2; p++) {
                int krow = k0 + selB_k + lrow;
                int ncol = wc + 16 * p + selB_n;
                uint32_t addr = sB + krow * (2 * OUTC) + ((2 * ncol) ^ ((krow & 7) * 16));
                LDSM_X4T(b[2 * p][0], b[2 * p][1], b[2 * p + 1][0], b[2 * p + 1][1], addr);
            }
            #pragma unroll
            for (int mt = 0; mt < 2; mt++)
                #pragma unroll
                for (int nt = 0; nt < NT; nt++)
                    mma_f16(acc[mt][nt], a[mt], b[nt]);
        }

        if (chunk + 1 < NCHUNK) {
            __syncthreads();   // all compute reads done before overwrite
            stAB();
            __syncthreads();   // new tiles visible
        }
    }

    #pragma unroll
    for (int mt = 0; mt < 2; mt++) {
        #pragma unroll
        for (int nt = 0; nt < NT; nt++) {
            int col = wc + 8 * nt + 2 * t;
            float bx = bias[col], by = bias[col + 1];
            int row0 = nb + wn + 16 * mt + g;
            int row1 = row0 + 8;
            float v0 = acc[mt][nt][0] + bx, v1 = acc[mt][nt][1] + by;
            float v2 = acc[mt][nt][2] + bx, v3 = acc[mt][nt][3] + by;
            if (RELU) {
                v0 = fmaxf(v0, 0.f); v1 = fmaxf(v1, 0.f);
                v2 = fmaxf(v2, 0.f); v3 = fmaxf(v3, 0.f);
            }
            if (row0 < N) {
                __half2 h = __float22half2_rn(make_float2(v0, v1));
                *(uint32_t*)((__half*)out + (size_t)row0 * OUTC + col) = *(uint32_t*)&h;
            }
            if (row1 < N) {
                __half2 h = __float22half2_rn(make_float2(v2, v3));
                *(uint32_t*)((__half*)out + (size_t)row1 * OUTC + col) = *(uint32_t*)&h;
            }
        }
    }
}

// ---------------- launch ------------------------------------------------------
extern "C" void kernel_launch(void* const* d_in, const int* in_sizes, int n_in,
                              void* d_out, int out_size) {
    const float* x   = (const float*)d_in[0];
    const int*   ei  = (const int*)  d_in[1];
    const float* W1l = (const float*)d_in[2];
    const float* W1r = (const float*)d_in[3];
    const float* b1  = (const float*)d_in[4];
    const float* W2l = (const float*)d_in[5];
    const float* W2r = (const float*)d_in[6];
    const float* b2  = (const float*)d_in[7];
    const float* W3l = (const float*)d_in[8];
    const float* W3r = (const float*)d_in[9];
    const float* b3  = (const float*)d_in[10];
    float* out = (float*)d_out;

    int N = in_sizes[0] / HID;
    int E = in_sizes[1] / 2;
    const int* src = ei;
    const int* dst = ei + E;

    int*      deg;   cudaGetSymbolAddress((void**)&deg,   g_deg);
    int*      off;   cudaGetSymbolAddress((void**)&off,   g_off);
    int*      cur;   cudaGetSymbolAddress((void**)&cur,   g_cursor);
    int*      bsum;  cudaGetSymbolAddress((void**)&bsum,  g_bsum);
    uint16_t* srcs;  cudaGetSymbolAddress((void**)&srcs,  g_srcs);
    __half*   xh;    cudaGetSymbolAddress((void**)&xh,    g_xh);
    __half*   agg;   cudaGetSymbolAddress((void**)&agg,   g_agg);
    __half*   h1;    cudaGetSymbolAddress((void**)&h1,    g_h1);
    __half*   h2;    cudaGetSymbolAddress((void**)&h2,    g_h2);
    __half*   wh;    cudaGetSymbolAddress((void**)&wh,    g_wh);
    float*    b3cat; cudaGetSymbolAddress((void**)&b3cat, g_b3cat);

    int nblk = (N + 255) / 256;
    int e4blk = (E / 4 + 256) / 256;
    int eblk = (E + 255) / 256;
    int total8 = N * HID / 8;
    int xb = (total8 + 255) / 256;

    cudaMemsetAsync(deg, 0, (size_t)N * sizeof(int));
    prep_kernel<<<xb + 40 + e4blk, 256>>>(x, xh, xb, W1l, W1r, W2l, W2r, W3l, W3r,
                                          wh, b3, b3cat, dst, deg, E, total8);
    scan_partial<<<nblk, 256>>>(deg, off, bsum, N);
    finish_off<<<nblk, 256>>>(off, cur, bsum, N, nblk);
    fill_csr_kernel<<<eblk, 256>>>(src, dst, cur, srcs, E);

    int aggBlocks  = (N * 32 + 255) / 256;
    int gemmBlocks = (N + 127) / 128;
    size_t smem128 = 16384 + (size_t)128 * 128;  // 32 KB

    // layer 1
    agg_f16_kernel<<<aggBlocks, 256>>>(xh, agg, off, srcs, N);
    gemm_f16<128, true, __half, 4><<<gemmBlocks, 256, smem128>>>(
        agg, xh, wh, wh + 16384, b1, h1, N);
    // layer 2
    agg_f16_kernel<<<aggBlocks, 256>>>(h1, agg, off, srcs, N);
    gemm_f16<128, true, __half, 4><<<gemmBlocks, 256, smem128>>>(
        agg, h1, wh + 32768, wh + 49152, b2, h2, N);
    // layer 3: [p|q] = h2 @ [W3l|W3r] (+[0|b3]), then out = mean-gather(p) + q
    gemm_f16<128, false, __half, 2><<<gemmBlocks, 256, smem128>>>(
        h2, h2, wh + 65536, wh + 65536, b3cat, h1, N);
    final_agg_kernel<<<aggBlocks, 256>>>(h1, out, off, srcs, N);
}

// round 17
// speedup vs baseline: 1.4941x; 1.4941x over previous
#include <cuda_runtime.h>
#include <cuda_fp16.h>
#include <cstdint>

#define N_NODES 50000
#define N_EDGES 500000
#define HID 128

// ---------------- scratch (device globals) ------------------------------------
__device__ int      g_deg[N_NODES];
__device__ int      g_off[N_NODES + 1];
__device__ int      g_cursor[N_NODES];
__device__ int      g_bsum[256];
__device__ uint16_t g_srcs[N_EDGES];
__device__ __half   g_xh [(size_t)N_NODES * HID];
__device__ __half   g_agg[(size_t)N_NODES * HID];
__device__ __half   g_h1 [(size_t)N_NODES * HID];
__device__ __half   g_h2 [(size_t)N_NODES * HID];
__device__ __half   g_wh [81920];    // [W1l|W1r|W2l|W2r|Wcat3] fp16
__device__ float    g_b3cat[128];    // [0...0 | b3]

// ---------------- small helpers -----------------------------------------------
__device__ __forceinline__ uint32_t smem_u32(const void* p) {
    uint32_t a;
    asm("{ .reg .u64 t; cvta.to.shared.u64 t, %1; cvt.u32.u64 %0, t; }" : "=r"(a) : "l"(p));
    return a;
}

#define LDSM_X4(r, a) \
    asm volatile("ldmatrix.sync.aligned.m8n8.x4.shared.b16 {%0,%1,%2,%3}, [%4];" \
                 : "=r"((r)[0]), "=r"((r)[1]), "=r"((r)[2]), "=r"((r)[3]) : "r"(a))
#define LDSM_X4T(r0, r1, r2, r3, a) \
    asm volatile("ldmatrix.sync.aligned.m8n8.x4.trans.shared.b16 {%0,%1,%2,%3}, [%4];" \
                 : "=r"(r0), "=r"(r1), "=r"(r2), "=r"(r3) : "r"(a))

__device__ __forceinline__ void mma_f16(float* d, const uint32_t* a, const uint32_t* b) {
    asm volatile(
        "mma.sync.aligned.m16n8k16.row.col.f32.f16.f16.f32 "
        "{%0,%1,%2,%3}, {%4,%5,%6,%7}, {%8,%9}, {%0,%1,%2,%3};"
        : "+f"(d[0]), "+f"(d[1]), "+f"(d[2]), "+f"(d[3])
        : "r"(a[0]), "r"(a[1]), "r"(a[2]), "r"(a[3]), "r"(b[0]), "r"(b[1]));
}

__device__ __forceinline__ uint4 cvt8(const float* p) {
    float4 a = ((const float4*)p)[0], b = ((const float4*)p)[1];
    __half2 h0 = __float22half2_rn(make_float2(a.x, a.y));
    __half2 h1 = __float22half2_rn(make_float2(a.z, a.w));
    __half2 h2 = __float22half2_rn(make_float2(b.x, b.y));
    __half2 h3 = __float22half2_rn(make_float2(b.z, b.w));
    uint4 u;
    u.x = *(uint32_t*)&h0; u.y = *(uint32_t*)&h1;
    u.z = *(uint32_t*)&h2; u.w = *(uint32_t*)&h3;
    return u;
}

// ---------------- prep: conv_x + conv_w(+b3cat) + count_deg --------------------
__global__ void prep_kernel(const float* __restrict__ x, __half* __restrict__ xh, int xb,
                            const float* __restrict__ W1l, const float* __restrict__ W1r,
                            const float* __restrict__ W2l, const float* __restrict__ W2r,
                            const float* __restrict__ W3l, const float* __restrict__ W3r,
                            __half* __restrict__ wh,
                            const float* __restrict__ b3, float* __restrict__ b3cat,
                            const int* __restrict__ dst, int* __restrict__ deg, int E,
                            int total8) {
    int b = blockIdx.x, tid = threadIdx.x;
    if (b < xb) {
        int i = b * 256 + tid;
        if (i < total8)
            *(uint4*)(xh + (size_t)i * 8) = cvt8(x + (size_t)i * 8);
    } else if (b < xb + 40) {
        if (b == xb && tid < 128)
            b3cat[tid] = (tid < 64) ? 0.f : b3[tid - 64];
        int i = (b - xb) * 256 + tid;
        if (i < 10240) {
            int base = i * 8;
            const float* src;
            if      (base < 16384) { src = W1l + base;         }
            else if (base < 32768) { src = W1r + base - 16384; }
            else if (base < 49152) { src = W2l + base - 32768; }
            else if (base < 65536) { src = W2r + base - 49152; }
            else {
                int loc = base - 65536;         // Wcat: [128 k][128 c]
                int k = loc >> 7, c = loc & 127;
                src = (c < 64) ? (W3l + k * 64 + c) : (W3r + k * 64 + c - 64);
            }
            *(uint4*)(wh + base) = cvt8(src);
        }
    } else {
        // degree count, 4 edges per thread (fire-and-forget atomics)
        int e4 = (b - xb - 40) * 256 + tid;
        int base = e4 * 4;
        if (base + 3 < E) {
            int4 d = *(const int4*)(dst + base);
            atomicAdd(&deg[d.x], 1);
            atomicAdd(&deg[d.y], 1);
            atomicAdd(&deg[d.z], 1);
            atomicAdd(&deg[d.w], 1);
        } else if (base < E) {
            for (int k = base; k < E; k++) atomicAdd(&deg[dst[k]], 1);
        }
    }
}

// ---------------- two-kernel scan ----------------------------------------------
__device__ __forceinline__ int block_scan256(int v, int* ws) {
    int lane = threadIdx.x & 31, w = threadIdx.x >> 5;
    int x = v;
    #pragma unroll
    for (int o = 1; o < 32; o <<= 1) {
        int t = __shfl_up_sync(0xFFFFFFFFu, x, o);
        if (lane >= o) x += t;
    }
    if (lane == 31) ws[w] = x;
    __syncthreads();
    if (w == 0) {
        int y = (lane < 8) ? ws[lane] : 0;
        #pragma unroll
        for (int o = 1; o < 8; o <<= 1) {
            int t = __shfl_up_sync(0xFFFFFFFFu, y, o);
            if (lane >= o) y += t;
        }
        if (lane < 8) ws[lane] = y;
    }
    __syncthreads();
    int base = (w > 0) ? ws[w - 1] : 0;
    return x + base;
}

__global__ void scan_partial(const int* __restrict__ deg, int* __restrict__ off,
                             int* __restrict__ bsum, int N) {
    __shared__ int ws[8];
    int i = blockIdx.x * 256 + threadIdx.x;
    int v = (i < N) ? deg[i] : 0;
    int incl = block_scan256(v, ws);
    if (i < N) off[i] = incl - v;
    if (threadIdx.x == 255) bsum[blockIdx.x] = incl;
}

__device__ __forceinline__ int block_reduce256(int v, int* ws) {
    int lane = threadIdx.x & 31, w = threadIdx.x >> 5;
    #pragma unroll
    for (int o = 16; o > 0; o >>= 1) v += __shfl_down_sync(0xFFFFFFFFu, v, o);
    if (lane == 0) ws[w] = v;
    __syncthreads();
    if (w == 0) {
        int y = (lane < 8) ? ws[lane] : 0;
        #pragma unroll
        for (int o = 4; o > 0; o >>= 1) y += __shfl_down_sync(0xFFFFFFFFu, y, o);
        if (lane == 0) ws[0] = y;
    }
    __syncthreads();
    return ws[0];
}

__global__ void finish_off(int* __restrict__ off, int* __restrict__ cur,
                           const int* __restrict__ bsum, int N, int nblk) {
    __shared__ int ws[8];
    __shared__ int s_prefix;
    int b = blockIdx.x, t = threadIdx.x;
    int v = (t < b) ? bsum[t] : 0;
    int pre = block_reduce256(v, ws);
    if (t == 0) s_prefix = pre;
    __syncthreads();
    int i = b * 256 + t;
    if (i < N) {
        int val = off[i] + s_prefix;
        off[i] = val;
        cur[i] = val;
    }
    if (b == 0) {
        __syncthreads();
        int v2 = (t < nblk) ? bsum[t] : 0;
        int total = block_reduce256(v2, ws);
        if (t == 0) off[N] = total;
    }
}

// ---------------- CSR fill: 1 edge per thread (confirmed optimal) --------------
__global__ void fill_csr_kernel(const int* __restrict__ src, const int* __restrict__ dst,
                                int* __restrict__ cur, uint16_t* __restrict__ srcs, int E) {
    int e = blockIdx.x * blockDim.x + threadIdx.x;
    if (e < E) {
        int pos = atomicAdd(&cur[dst[e]], 1);
        srcs[pos] = (uint16_t)src[e];
    }
}

// ---------------- mean aggregation (warp/node, uint2, pairwise-8 tree) ---------
__global__ void agg_f16_kernel(const __half* __restrict__ x, __half* __restrict__ agg,
                               const int* __restrict__ off,
                               const uint16_t* __restrict__ srcs, int N) {
    int warp = (blockIdx.x * blockDim.x + threadIdx.x) >> 5;
    int lane = threadIdx.x & 31;
    if (warp >= N) return;
    int s = off[warp], e = off[warp + 1];
    float4 acc = make_float4(0.f, 0.f, 0.f, 0.f);
    int j = s;
    for (; j + 7 < e; j += 8) {
        uint2 p0 = *(const uint2*)(x + (size_t)srcs[j + 0] * HID + 4 * lane);
        uint2 p1 = *(const uint2*)(x + (size_t)srcs[j + 1] * HID + 4 * lane);
        uint2 p2 = *(const uint2*)(x + (size_t)srcs[j + 2] * HID + 4 * lane);
        uint2 p3 = *(const uint2*)(x + (size_t)srcs[j + 3] * HID + 4 * lane);
        uint2 p4 = *(const uint2*)(x + (size_t)srcs[j + 4] * HID + 4 * lane);
        uint2 p5 = *(const uint2*)(x + (size_t)srcs[j + 5] * HID + 4 * lane);
        uint2 p6 = *(const uint2*)(x + (size_t)srcs[j + 6] * HID + 4 * lane);
        uint2 p7 = *(const uint2*)(x + (size_t)srcs[j + 7] * HID + 4 * lane);
        __half2 slo = __hadd2(
            __hadd2(__hadd2(*(__half2*)&p0.x, *(__half2*)&p1.x),
                    __hadd2(*(__half2*)&p2.x, *(__half2*)&p3.x)),
            __hadd2(__hadd2(*(__half2*)&p4.x, *(__half2*)&p5.x),
                    __hadd2(*(__half2*)&p6.x, *(__half2*)&p7.x)));
        __half2 shi = __hadd2(
            __hadd2(__hadd2(*(__half2*)&p0.y, *(__half2*)&p1.y),
                    __hadd2(*(__half2*)&p2.y, *(__half2*)&p3.y)),
            __hadd2(__hadd2(*(__half2*)&p4.y, *(__half2*)&p5.y),
                    __hadd2(*(__half2*)&p6.y, *(__half2*)&p7.y)));
        float2 flo = __half22float2(slo);
        float2 fhi = __half22float2(shi);
        acc.x += flo.x; acc.y += flo.y; acc.z += fhi.x; acc.w += fhi.y;
    }
    if (j + 3 < e) {
        uint2 p0 = *(const uint2*)(x + (size_t)srcs[j + 0] * HID + 4 * lane);
        uint2 p1 = *(const uint2*)(x + (size_t)srcs[j + 1] * HID + 4 * lane);
        uint2 p2 = *(const uint2*)(x + (size_t)srcs[j + 2] * HID + 4 * lane);
        uint2 p3 = *(const uint2*)(x + (size_t)srcs[j + 3] * HID + 4 * lane);
        __half2 slo = __hadd2(__hadd2(*(__half2*)&p0.x, *(__half2*)&p1.x),
                              __hadd2(*(__half2*)&p2.x, *(__half2*)&p3.x));
        __half2 shi = __hadd2(__hadd2(*(__half2*)&p0.y, *(__half2*)&p1.y),
                              __hadd2(*(__half2*)&p2.y, *(__half2*)&p3.y));
        float2 flo = __half22float2(slo);
        float2 fhi = __half22float2(shi);
        acc.x += flo.x; acc.y += flo.y; acc.z += fhi.x; acc.w += fhi.y;
        j += 4;
    }
    for (; j < e; j++) {
        uint2 p0 = *(const uint2*)(x + (size_t)srcs[j] * HID + 4 * lane);
        float2 a0 = __half22float2(*(__half2*)&p0.x), a1 = __half22float2(*(__half2*)&p0.y);
        acc.x += a0.x; acc.y += a0.y; acc.z += a1.x; acc.w += a1.y;
    }
    float inv = 1.0f / (float)max(e - s, 1);
    __half2 o0 = __float22half2_rn(make_float2(acc.x * inv, acc.y * inv));
    __half2 o1 = __float22half2_rn(make_float2(acc.z * inv, acc.w * inv));
    uint2 o;
    o.x = *(uint32_t*)&o0; o.y = *(uint32_t*)&o1;
    *(uint2*)(agg + (size_t)warp * HID + 4 * lane) = o;
}

// ---------------- layer-3 final: out = mean-gather(p) + q ----------------------
__global__ void final_agg_kernel(const __half* __restrict__ ph, float* __restrict__ out,
                                 const int* __restrict__ off,
                                 const uint16_t* __restrict__ srcs, int N) {
    int warp = (blockIdx.x * blockDim.x + threadIdx.x) >> 5;
    int lane = threadIdx.x & 31;
    if (warp >= N) return;
    int s = off[warp], e = off[warp + 1];
    float2 acc = make_float2(0.f, 0.f);
    int j = s;
    for (; j + 7 < e; j += 8) {
        __half2 h0 = *(const __half2*)(ph + (size_t)srcs[j + 0] * HID + 2 * lane);
        __half2 h1 = *(const __half2*)(ph + (size_t)srcs[j + 1] * HID + 2 * lane);
        __half2 h2 = *(const __half2*)(ph + (size_t)srcs[j + 2] * HID + 2 * lane);
        __half2 h3 = *(const __half2*)(ph + (size_t)srcs[j + 3] * HID + 2 * lane);
        __half2 h4 = *(const __half2*)(ph + (size_t)srcs[j + 4] * HID + 2 * lane);
        __half2 h5 = *(const __half2*)(ph + (size_t)srcs[j + 5] * HID + 2 * lane);
        __half2 h6 = *(const __half2*)(ph + (size_t)srcs[j + 6] * HID + 2 * lane);
        __half2 h7 = *(const __half2*)(ph + (size_t)srcs[j + 7] * HID + 2 * lane);
        __half2 sh = __hadd2(__hadd2(__hadd2(h0, h1), __hadd2(h2, h3)),
                             __hadd2(__hadd2(h4, h5), __hadd2(h6, h7)));
        float2 f = __half22float2(sh);
        acc.x += f.x; acc.y += f.y;
    }
    if (j + 3 < e) {
        __half2 h0 = *(const __half2*)(ph + (size_t)srcs[j + 0] * HID + 2 * lane);
        __half2 h1 = *(const __half2*)(ph + (size_t)srcs[j + 1] * HID + 2 * lane);
        __half2 h2 = *(const __half2*)(ph + (size_t)srcs[j + 2] * HID + 2 * lane);
        __half2 h3 = *(const __half2*)(ph + (size_t)srcs[j + 3] * HID + 2 * lane);
        __half2 sh = __hadd2(__hadd2(h0, h1), __hadd2(h2, h3));
        float2 f = __half22float2(sh);
        acc.x += f.x; acc.y += f.y;
        j += 4;
    }
    for (; j < e; j++) {
        float2 f0 = __half22float2(*(const __half2*)(ph + (size_t)srcs[j] * HID + 2 * lane));
        acc.x += f0.x; acc.y += f0.y;
    }
    float inv = 1.0f / (float)max(e - s, 1);
    float2 q = __half22float2(*(const __half2*)(ph + (size_t)warp * HID + 64 + 2 * lane));
    *(float2*)(out + (size_t)warp * 64 + 2 * lane) =
        make_float2(acc.x * inv + q.x, acc.y * inv + q.y);
}

// ---------------- fp16 tensor-core GEMM ----------------------------------------
template <int OUTC, bool RELU, typename OT, int NCHUNK>
__global__ __launch_bounds__(256, 2)
void gemm_f16(const __half* __restrict__ agg, const __half* __restrict__ xin,
              const __half* __restrict__ Whl, const __half* __restrict__ Whr,
              const float* __restrict__ bias, OT* __restrict__ out, int N) {
    constexpr int NT = OUTC / 16;
    extern __shared__ char smem[];
    uint32_t sA = smem_u32(smem);
    uint32_t sB = sA + 16384;

    int tid = threadIdx.x, lane = tid & 31, wid = tid >> 5;
    int nb = blockIdx.x * 128;
    int wn = 32 * (wid >> 1);
    int wc = (OUTC / 2) * (wid & 1);
    int g  = lane >> 2;
    int t  = lane & 3;
    int lrow = lane & 7;
    int selA_r = ((lane >> 3) & 1) * 8;
    int selA_k = ((lane >> 4) & 1) * 8;
    int selB_k = ((lane >> 3) & 1) * 8;
    int selB_n = ((lane >> 4) & 1) * 8;

    float acc[2][NT][4];
    #pragma unroll
    for (int mt = 0; mt < 2; mt++)
        #pragma unroll
        for (int nt = 0; nt < NT; nt++)
            #pragma unroll
            for (int q = 0; q < 4; q++) acc[mt][nt][q] = 0.f;

    #pragma unroll
    for (int chunk = 0; chunk < NCHUNK; chunk++) {
        const __half* Asrc = (chunk < 2) ? agg : xin;
        const __half* Wsrc = (chunk < 2) ? Whl : Whr;
        int kb = (chunk & 1) * 64;

        __syncthreads();

        #pragma unroll
        for (int it = 0; it < 4; it++) {
            int idx = it * 256 + tid;
            int node = idx >> 3, u8 = idx & 7;
            int gn = min(nb + node, N - 1);
            uint4 v = *(const uint4*)(Asrc + (size_t)gn * HID + kb + 8 * u8);
            uint32_t off = node * 128 + ((u8 * 16) ^ ((node & 7) * 16));
            *(uint4*)(smem + off) = v;
        }
        constexpr int BTASK = 64 * (OUTC / 8);
        #pragma unroll
        for (int it = 0; it < BTASK / 256; it++) {
            int idx = it * 256 + tid;
            int k = idx / (OUTC / 8), u = idx % (OUTC / 8);
            uint4 v = *(const uint4*)(Wsrc + (size_t)(kb + k) * OUTC + 8 * u);
            uint32_t o = k * (2 * OUTC) + ((u * 16) ^ ((k & 7) * 16));
            *(uint4*)(smem + 16384 + o) = v;
        }
        __syncthreads();

        #pragma unroll
        for (int ks = 0; ks < 4; ks++) {
            int k0 = 16 * ks;
            uint32_t a[2][4];
            #pragma unroll
            for (int mt = 0; mt < 2; mt++) {
                int row = wn + 16 * mt + selA_r + lrow;
                int kc  = k0 + selA_k;
                uint32_t addr = sA + row * 128 + ((2 * kc) ^ ((row & 7) * 16));
                LDSM_X4(a[mt], addr);
            }
            uint32_t b[NT][2];
            #pragma unroll
            for (int p = 0; p < NT / 2; p++) {
                int krow = k0 + selB_k + lrow;
                int ncol = wc + 16 * p + selB_n;
                uint32_t addr = sB + krow * (2 * OUTC) + ((2 * ncol) ^ ((krow & 7) * 16));
                LDSM_X4T(b[2 * p][0], b[2 * p][1], b[2 * p + 1][0], b[2 * p + 1][1], addr);
            }
            #pragma unroll
            for (int mt = 0; mt < 2; mt++)
                #pragma unroll
                for (int nt = 0; nt < NT; nt++)
                    mma_f16(acc[mt][nt], a[mt], b[nt]);
        }
    }

    #pragma unroll
    for (int mt = 0; mt < 2; mt++) {
        #pragma unroll
        for (int nt = 0; nt < NT; nt++) {
            int col = wc + 8 * nt + 2 * t;
            float bx = bias[col], by = bias[col + 1];
            int row0 = nb + wn + 16 * mt + g;
            int row1 = row0 + 8;
            float v0 = acc[mt][nt][0] + bx, v1 = acc[mt][nt][1] + by;
            float v2 = acc[mt][nt][2] + bx, v3 = acc[mt][nt][3] + by;
            if (RELU) {
                v0 = fmaxf(v0, 0.f); v1 = fmaxf(v1, 0.f);
                v2 = fmaxf(v2, 0.f); v3 = fmaxf(v3, 0.f);
            }
            if (row0 < N) {
                __half2 h = __float22half2_rn(make_float2(v0, v1));
                *(uint32_t*)((__half*)out + (size_t)row0 * OUTC + col) = *(uint32_t*)&h;
            }
            if (row1 < N) {
                __half2 h = __float22half2_rn(make_float2(v2, v3));
                *(uint32_t*)((__half*)out + (size_t)row1 * OUTC + col) = *(uint32_t*)&h;
            }
        }
    }
}

// ---------------- launch ------------------------------------------------------
extern "C" void kernel_launch(void* const* d_in, const int* in_sizes, int n_in,
                              void* d_out, int out_size) {
    const float* x   = (const float*)d_in[0];
    const int*   ei  = (const int*)  d_in[1];
    const float* W1l = (const float*)d_in[2];
    const float* W1r = (const float*)d_in[3];
    const float* b1  = (const float*)d_in[4];
    const float* W2l = (const float*)d_in[5];
    const float* W2r = (const float*)d_in[6];
    const float* b2  = (const float*)d_in[7];
    const float* W3l = (const float*)d_in[8];
    const float* W3r = (const float*)d_in[9];
    const float* b3  = (const float*)d_in[10];
    float* out = (float*)d_out;

    int N = in_sizes[0] / HID;
    int E = in_sizes[1] / 2;
    const int* src = ei;
    const int* dst = ei + E;

    int*      deg;   cudaGetSymbolAddress((void**)&deg,   g_deg);
    int*      off;   cudaGetSymbolAddress((void**)&off,   g_off);
    int*      cur;   cudaGetSymbolAddress((void**)&cur,   g_cursor);
    int*      bsum;  cudaGetSymbolAddress((void**)&bsum,  g_bsum);
    uint16_t* srcs;  cudaGetSymbolAddress((void**)&srcs,  g_srcs);
    __half*   xh;    cudaGetSymbolAddress((void**)&xh,    g_xh);
    __half*   agg;   cudaGetSymbolAddress((void**)&agg,   g_agg);
    __half*   h1;    cudaGetSymbolAddress((void**)&h1,    g_h1);
    __half*   h2;    cudaGetSymbolAddress((void**)&h2,    g_h2);
    __half*   wh;    cudaGetSymbolAddress((void**)&wh,    g_wh);
    float*    b3cat; cudaGetSymbolAddress((void**)&b3cat, g_b3cat);

    int nblk = (N + 255) / 256;
    int e4blk = (E / 4 + 256) / 256;
    int eblk = (E + 255) / 256;
    int total8 = N * HID / 8;
    int xb = (total8 + 255) / 256;

    cudaMemsetAsync(deg, 0, (size_t)N * sizeof(int));
    prep_kernel<<<xb + 40 + e4blk, 256>>>(x, xh, xb, W1l, W1r, W2l, W2r, W3l, W3r,
                                          wh, b3, b3cat, dst, deg, E, total8);
    scan_partial<<<nblk, 256>>>(deg, off, bsum, N);
    finish_off<<<nblk, 256>>>(off, cur, bsum, N, nblk);
    fill_csr_kernel<<<eblk, 256>>>(src, dst, cur, srcs, E);

    int aggBlocks  = (N * 32 + 255) / 256;
    int gemmBlocks = (N + 127) / 128;
    size_t smem128 = 16384 + (size_t)128 * 128;  // 32 KB

    // layer 1
    agg_f16_kernel<<<aggBlocks, 256>>>(xh, agg, off, srcs, N);
    gemm_f16<128, true, __half, 4><<<gemmBlocks, 256, smem128>>>(
        agg, xh, wh, wh + 16384, b1, h1, N);
    // layer 2
    agg_f16_kernel<<<aggBlocks, 256>>>(h1, agg, off, srcs, N);
    gemm_f16<128, true, __half, 4><<<gemmBlocks, 256, smem128>>>(
        agg, h1, wh + 32768, wh + 49152, b2, h2, N);
    // layer 3: [p|q] = h2 @ [W3l|W3r] (+[0|b3]), then out = mean-gather(p) + q
    gemm_f16<128, false, __half, 2><<<gemmBlocks, 256, smem128>>>(
        h2, h2, wh + 65536, wh + 65536, b3cat, h1, N);
    final_agg_kernel<<<aggBlocks, 256>>>(h1, out, off, srcs, N);
}